// round 6
// baseline (speedup 1.0000x reference)
#include <cuda_runtime.h>
#include <cuda_fp16.h>
#include <math.h>
#include <stdint.h>

// ---------------------------------------------------------------------------
// Problem constants
// ---------------------------------------------------------------------------
#define BSZ   64
#define IMG   128
#define CH    24
#define QD    11
#define AD    10
#define NN    64      // objects per image (8x8)
#define FD    26      // CH + 2 coords
#define HID   256
#define EPSV  1e-5f

// rn_mma geometry (fp16)
#define M_CTA     128            // pair rows per CTA (2 i-values x 64 j)
#define SA        264            // half-element stride for row-major h1
#define WSLAB_B   32768          // 4 k16-steps of fragment-ordered fp16 weights
#define N_SLABS   12             // 3 layers x 4 slabs
#define HROW_OFF  (2*WSLAB_B)                 // 65536
#define FRAG_OFF  (HROW_OFF + M_CTA*SA*2)     // 133120
#define DYN_RN    (FRAG_OFF + 65536)          // 198656

// ---------------------------------------------------------------------------
// Scratch
// ---------------------------------------------------------------------------
__device__ float  g_x1[BSZ*CH*64*64];
__device__ float  g_x2[BSZ*CH*32*32];
__device__ float  g_x3[BSZ*CH*16*16];
__device__ float  g_x4[BSZ*CH*8*8];
__device__ float  g_gsum[BSZ*HID];
__device__ uint2  g_wf[3*16*32*32];    // fragment-ordered fp16 weights
__device__ float  g_bnsum[4*CH];
__device__ float  g_bnsq [4*CH];

// ---------------------------------------------------------------------------
// Helpers
// ---------------------------------------------------------------------------
__device__ __forceinline__ uint32_t smem_u32(const void* p) {
    uint32_t a;
    asm("{ .reg .u64 t; cvta.to.shared.u64 t, %1; cvt.u32.u64 %0, t; }"
        : "=r"(a) : "l"(p));
    return a;
}
__device__ __forceinline__ void mma_f16(float* c, const uint32_t* a,
                                        uint32_t b0, uint32_t b1) {
    asm volatile(
        "mma.sync.aligned.m16n8k16.row.col.f32.f16.f16.f32 "
        "{%0,%1,%2,%3}, {%4,%5,%6,%7}, {%8,%9}, {%0,%1,%2,%3};"
        : "+f"(c[0]), "+f"(c[1]), "+f"(c[2]), "+f"(c[3])
        : "r"(a[0]), "r"(a[1]), "r"(a[2]), "r"(a[3]), "r"(b0), "r"(b1));
}
__device__ __forceinline__ void ldsm_x4(uint32_t* a, uint32_t addr) {
    asm volatile("ldmatrix.sync.aligned.m8n8.x4.shared.b16 {%0,%1,%2,%3}, [%4];"
                 : "=r"(a[0]), "=r"(a[1]), "=r"(a[2]), "=r"(a[3]) : "r"(addr));
}
__device__ __forceinline__ void cp16(uint32_t dst, const void* src) {
    asm volatile("cp.async.cg.shared.global [%0], [%1], 16;"
                 :: "r"(dst), "l"(__cvta_generic_to_global(src)) : "memory");
}
#define CP_COMMIT() asm volatile("cp.async.commit_group;" ::: "memory")
#define CP_WAIT1()  asm volatile("cp.async.wait_group 1;" ::: "memory")
#define CP_WAIT0()  asm volatile("cp.async.wait_group 0;" ::: "memory")

__device__ __forceinline__ uint32_t pack_h2(float lo, float hi) {
    __half2 h = __floats2half2_rn(lo, hi);
    return *(uint32_t*)&h;
}

// ---------------------------------------------------------------------------
// Launch #1: fragment-ordered fp16 weights + zero accumulators
// ---------------------------------------------------------------------------
__global__ void wfrag_zero_kernel(const float* __restrict__ gw2,
                                  const float* __restrict__ gw3,
                                  const float* __restrict__ gw4,
                                  uint2* __restrict__ wf,
                                  float* __restrict__ gsum,
                                  float* __restrict__ bnsum,
                                  float* __restrict__ bnsq) {
    int idx = blockIdx.x * blockDim.x + threadIdx.x;   // [0, 3*16384)
    if (idx < BSZ*HID) gsum[idx] = 0.f;
    if (idx < 4*CH) { bnsum[idx] = 0.f; bnsq[idx] = 0.f; }
    if (idx >= 3*16384) return;
    int l  = idx >> 14;
    int r  = idx & 16383;
    int k  = r >> 10;
    int jg = (r >> 5) & 31;
    int t  = r & 31;
    const float* g = (l == 0) ? gw2 : (l == 1) ? gw3 : gw4;
    int n  = jg*8 + (t >> 2);
    int kk = k*16 + 2*(t & 3);
    uint2 val;
    val.x = pack_h2(g[(size_t)kk*HID + n],     g[(size_t)(kk+1)*HID + n]);
    val.y = pack_h2(g[(size_t)(kk+8)*HID + n], g[(size_t)(kk+9)*HID + n]);
    wf[idx] = val;
}

// ---------------------------------------------------------------------------
// Launches #2-5: fused conv (k=3,s=2,p=1) + inline input-BN finalize+apply
//                + bias + ReLU + output channel stats.
// ---------------------------------------------------------------------------
template<int CI, int CO, int HIN, int HOUT, int HW_IN, bool APPLY>
__global__ void conv_bn_kernel(const float* __restrict__ in,
                               const float* __restrict__ w,
                               const float* __restrict__ bias,
                               const float* __restrict__ sum_in,
                               const float* __restrict__ sq_in,
                               const float* __restrict__ bg_in,
                               const float* __restrict__ bb_in,
                               float* __restrict__ out,
                               float* __restrict__ sum_g,
                               float* __restrict__ sq_g) {
    __shared__ float ws[CI*CO*9];
    __shared__ float bs[CO];
    __shared__ float sci[CI], shi[CI];
    __shared__ float csum[CO], csq[CO];
    for (int i = threadIdx.x; i < CI*CO*9; i += blockDim.x) ws[i] = w[i];
    if (threadIdx.x < CO) {
        bs[threadIdx.x] = bias[threadIdx.x];
        csum[threadIdx.x] = 0.f; csq[threadIdx.x] = 0.f;
    }
    if (APPLY && threadIdx.x < CI) {
        int c = threadIdx.x;
        float cnt = (float)(BSZ * HW_IN);
        float m   = sum_in[c] / cnt;
        float var = sq_in[c] / cnt - m * m;
        float inv = rsqrtf(var + EPSV);
        float sc  = bg_in[c] * inv;
        sci[c] = sc;
        shi[c] = bb_in[c] - m * sc;
    }
    __syncthreads();

    int idx = blockIdx.x * blockDim.x + threadIdx.x;
    int ox = idx % HOUT;
    int oy = (idx / HOUT) % HOUT;
    int co = (idx / (HOUT*HOUT)) % CO;
    int b  = idx / (HOUT*HOUT*CO);

    float acc = bs[co];
    int iy0 = oy*2 - 1, ix0 = ox*2 - 1;
    #pragma unroll
    for (int ci = 0; ci < CI; ci++) {
        const float* ip = in + ((size_t)(b*CI + ci) * HIN) * HIN;
        const float* wp = ws + (co*CI + ci) * 9;
        float sc = APPLY ? sci[ci] : 1.f;
        float sh = APPLY ? shi[ci] : 0.f;
        #pragma unroll
        for (int ky = 0; ky < 3; ky++) {
            int iy = iy0 + ky;
            if (iy < 0 || iy >= HIN) continue;
            #pragma unroll
            for (int kx = 0; kx < 3; kx++) {
                int ix = ix0 + kx;
                if (ix < 0 || ix >= HIN) continue;
                float raw = ip[iy*HIN + ix];
                float x = APPLY ? (raw*sc + sh) : raw;
                acc += x * wp[ky*3 + kx];
            }
        }
    }
    float val = fmaxf(acc, 0.f);
    out[idx] = val;

    float s = val, s2 = val*val;
    #pragma unroll
    for (int off = 16; off > 0; off >>= 1) {
        s  += __shfl_xor_sync(0xFFFFFFFFu, s,  off);
        s2 += __shfl_xor_sync(0xFFFFFFFFu, s2, off);
    }
    if ((threadIdx.x & 31) == 0) {
        atomicAdd(&csum[co], s);
        atomicAdd(&csq [co], s2);
    }
    __syncthreads();
    if (threadIdx.x < CO) {
        if (csum[threadIdx.x] != 0.f) atomicAdd(&sum_g[threadIdx.x], csum[threadIdx.x]);
        if (csq [threadIdx.x] != 0.f) atomicAdd(&sq_g [threadIdx.x], csq [threadIdx.x]);
    }
}

// ---------------------------------------------------------------------------
// Launch #6: the relational core, now with fused prologue:
//   BN4 finalize + object features + layer-1 factorization (U2/V/S) + h1,
//   then 3x fp16 tensor-core GEMM layers + pair-mean reduction.
// ---------------------------------------------------------------------------
__global__ void __launch_bounds__(512, 1)
rn_mma_kernel(const float* __restrict__ x4, const float* __restrict__ q,
              const float* __restrict__ bnsum4, const float* __restrict__ bnsq4,
              const float* __restrict__ bg4, const float* __restrict__ bb4,
              const float* __restrict__ gw1, const float* __restrict__ gb1,
              float* __restrict__ gsum, const uint2* __restrict__ wf,
              const float* __restrict__ gb2, const float* __restrict__ gb3,
              const float* __restrict__ gb4) {
    extern __shared__ char dyn[];
    __half* hAh   = (__half*)(dyn + HROW_OFF);
    uint4*  frag4 = (uint4*)(dyn + FRAG_OFF);
    float*  Vbuf  = (float*)(dyn + FRAG_OFF);   // V staging (dies before frag4 use)
    float*  gw1s  = (float*)dyn;                // v-slice of gw1 (dies before weights)
    const uint2* wbuf2 = (const uint2*)dyn;
    const uint32_t wsm = smem_u32(dyn);
    const uint32_t hA_addr = smem_u32(hAh);
    __shared__ float biasS[3*HID];
    __shared__ float colsum[HID];
    __shared__ float oS[FD*NN];
    __shared__ float U2s[2*HID];
    __shared__ float sS[HID];
    __shared__ float sc4[CH], sh4[CH];
    __shared__ float qS[QD];

    const int tid  = threadIdx.x;
    const int lane = tid & 31;
    const int warp = tid >> 5;
    const int mg   = warp & 3;
    const int ng   = warp >> 2;
    const int tig  = lane & 3;
    const int lm_row = (lane & 7) + ((lane & 8) ? 8 : 0);
    const int lm_col = (lane & 16) ? 8 : 0;

    const int b  = blockIdx.x >> 5;
    const int i0 = (blockIdx.x & 31) * 2;

    // ---- prologue stage 0: biases, BN4 finalize, q, gw1 v-slice ----
    for (int i = tid; i < HID; i += 512) {
        biasS[i]         = gb2[i];
        biasS[HID + i]   = gb3[i];
        biasS[2*HID + i] = gb4[i];
    }
    if (tid < HID) colsum[tid] = 0.f;
    if (tid < CH) {
        float cnt = (float)(BSZ * 64);
        float m   = bnsum4[tid] / cnt;
        float var = bnsq4[tid] / cnt - m * m;
        float inv = rsqrtf(var + EPSV);
        float sc  = bg4[tid] * inv;
        sc4[tid] = sc;
        sh4[tid] = bb4[tid] - m * sc;
    }
    if (tid >= 32 && tid < 32 + QD) qS[tid - 32] = q[b*QD + tid - 32];
    // stage gw1 rows [26,52) (v-part), 26*256 floats = 1664 float4
    for (int i = tid; i < FD*HID/4; i += 512)
        ((float4*)gw1s)[i] = ((const float4*)(gw1 + FD*HID))[i];
    __syncthreads();

    // ---- prologue stage 1: object features oS[f][n] ----
    for (int i = tid; i < CH*NN; i += 512) {
        int c = i >> 6, n = i & 63;
        oS[c*NN + n] = x4[(size_t)(b*CH + c)*NN + n] * sc4[c] + sh4[c];
    }
    if (tid < NN) {
        oS[24*NN + tid] = (float)(tid >> 3) * 0.125f;
        oS[25*NN + tid] = (float)(tid & 7)  * 0.125f;
    }
    __syncthreads();

    // ---- prologue stage 2: V[64][256], U2[2][256], S[256] ----
    {
        const int j0 = (tid >> 6) * 8;
        const int c0 = (tid & 63) * 4;
        float vacc[8][4];
        #pragma unroll
        for (int jj = 0; jj < 8; jj++)
            #pragma unroll
            for (int cc = 0; cc < 4; cc++) vacc[jj][cc] = 0.f;
        #pragma unroll
        for (int f = 0; f < FD; f++) {
            float4 wv = *(const float4*)(gw1s + f*HID + c0);
            #pragma unroll
            for (int jj = 0; jj < 8; jj++) {
                float ov = oS[f*NN + j0 + jj];
                vacc[jj][0] += ov * wv.x;
                vacc[jj][1] += ov * wv.y;
                vacc[jj][2] += ov * wv.z;
                vacc[jj][3] += ov * wv.w;
            }
        }
        #pragma unroll
        for (int jj = 0; jj < 8; jj++)
            *(float4*)(Vbuf + (j0 + jj)*HID + c0) =
                make_float4(vacc[jj][0], vacc[jj][1], vacc[jj][2], vacc[jj][3]);
    }
    {
        const int ih = tid >> 8;
        const int c  = tid & 255;
        float ua = 0.f;
        #pragma unroll
        for (int f = 0; f < FD; f++)
            ua += oS[f*NN + i0 + ih] * gw1[(size_t)f*HID + c];
        U2s[ih*HID + c] = ua;
        if (tid < HID) {
            float sa = gb1[c];
            #pragma unroll
            for (int t = 0; t < QD; t++)
                sa += qS[t] * gw1[(size_t)(2*FD + t)*HID + c];
            sS[c] = sa;
        }
    }
    __syncthreads();

    // ---- prefetch W slab 0 (overwrites gw1s region; safe after sync) ----
    {
        const char* src = (const char*)wf;
        #pragma unroll
        for (int i = 0; i < 4; i++)
            cp16(wsm + (i*512 + tid)*16, src + (i*512 + tid)*16);
        CP_COMMIT();
    }

    // ---- prologue stage 3: h1 (fp16, row-major) into hAh ----
    {
        const int row = tid >> 2;
        const int c0  = (tid & 3) * 64;
        const int ih  = row >> 6;
        const int jj  = row & 63;
        const float* up = U2s + ih*HID;
        const float* vp = Vbuf + jj*HID;
        #pragma unroll
        for (int f = 0; f < 8; f++) {
            int c = c0 + f*8;
            float4 u0 = *(const float4*)(up + c);
            float4 v0 = *(const float4*)(vp + c);
            float4 s0 = *(const float4*)(sS + c);
            float4 u1 = *(const float4*)(up + c + 4);
            float4 v1 = *(const float4*)(vp + c + 4);
            float4 s1 = *(const float4*)(sS + c + 4);
            uint4 hq;
            hq.x = pack_h2(fmaxf(u0.x+v0.x+s0.x, 0.f), fmaxf(u0.y+v0.y+s0.y, 0.f));
            hq.y = pack_h2(fmaxf(u0.z+v0.z+s0.z, 0.f), fmaxf(u0.w+v0.w+s0.w, 0.f));
            hq.z = pack_h2(fmaxf(u1.x+v1.x+s1.x, 0.f), fmaxf(u1.y+v1.y+s1.y, 0.f));
            hq.w = pack_h2(fmaxf(u1.z+v1.z+s1.z, 0.f), fmaxf(u1.w+v1.w+s1.w, 0.f));
            *(uint4*)(hAh + row*SA + c) = hq;
        }
    }

    float acc[2][8][4];

    #pragma unroll 1
    for (int sl = 0; sl < N_SLABS; sl++) {
        const int l   = sl >> 2;
        const int cur = sl & 1;
        __syncthreads();                       // prev compute done; stores visible
        if (sl + 1 < N_SLABS) {
            const char* src = (const char*)wf + (size_t)(sl + 1) * WSLAB_B;
            uint32_t dst = wsm + (cur ^ 1) * WSLAB_B;
            #pragma unroll
            for (int i = 0; i < 4; i++)
                cp16(dst + (i*512 + tid)*16, src + (i*512 + tid)*16);
            CP_COMMIT();
            CP_WAIT1();
        } else {
            CP_WAIT0();
        }
        __syncthreads();                       // slab sl visible to all

        if ((sl & 3) == 0) {
            #pragma unroll
            for (int mt = 0; mt < 2; mt++)
                #pragma unroll
                for (int j = 0; j < 8; j++)
                    #pragma unroll
                    for (int c = 0; c < 4; c++)
                        acc[mt][j][c] = 0.f;
        }

        const uint2* wslab = wbuf2 + cur * (WSLAB_B/8);
        if (l == 0) {
            // layer 1: A via ldmatrix from row-major h1
            #pragma unroll
            for (int kk = 0; kk < 4; kk++) {
                const int kcol = ((sl & 3)*4 + kk) * 16;
                uint32_t a[2][4];
                #pragma unroll
                for (int mt = 0; mt < 2; mt++) {
                    uint32_t addr = hA_addr +
                        (((mg*32 + mt*16 + lm_row) * SA) + kcol + lm_col) * 2;
                    ldsm_x4(a[mt], addr);
                }
                uint2 bbv[8];
                #pragma unroll
                for (int j = 0; j < 8; j++)
                    bbv[j] = wslab[(kk*32 + (ng*8 + j))*32 + lane];
                #pragma unroll
                for (int j = 0; j < 8; j++) {
                    mma_f16(acc[0][j], a[0], bbv[j].x, bbv[j].y);
                    mma_f16(acc[1][j], a[1], bbv[j].x, bbv[j].y);
                }
            }
        } else {
            // layers 2-3: A via one LDS.128 per 16x16 tile (fragment layout)
            #pragma unroll
            for (int kk = 0; kk < 4; kk++) {
                const int kkg = (sl & 3)*4 + kk;
                uint4 aq[2];
                aq[0] = frag4[((mg*2 + 0)*16 + kkg)*32 + lane];
                aq[1] = frag4[((mg*2 + 1)*16 + kkg)*32 + lane];
                uint2 bbv[8];
                #pragma unroll
                for (int j = 0; j < 8; j++)
                    bbv[j] = wslab[(kk*32 + (ng*8 + j))*32 + lane];
                #pragma unroll
                for (int j = 0; j < 8; j++) {
                    mma_f16(acc[0][j], (const uint32_t*)&aq[0], bbv[j].x, bbv[j].y);
                    mma_f16(acc[1][j], (const uint32_t*)&aq[1], bbv[j].x, bbv[j].y);
                }
            }
        }

        if ((sl & 3) == 3) {
            if (l < 2) {
                // epilogue: C frag == A frag layout; store STS.128 to frag4
                if (l == 1) __syncthreads();   // frag4 in-place overwrite
                const float* bl = biasS + l*HID;
                #pragma unroll
                for (int mt = 0; mt < 2; mt++) {
                    const int rb = mg*2 + mt;
                    #pragma unroll
                    for (int jp = 0; jp < 4; jp++) {
                        const int j = jp*2;
                        const int colE = ng*64 + j*8 + 2*tig;
                        const int colO = colE + 8;
                        float bE0 = biasS[l*HID + colE], bE1 = biasS[l*HID + colE+1];
                        float bO0 = biasS[l*HID + colO], bO1 = biasS[l*HID + colO+1];
                        (void)bl;
                        uint4 qv;
                        qv.x = pack_h2(fmaxf(acc[mt][j][0]+bE0, 0.f),
                                       fmaxf(acc[mt][j][1]+bE1, 0.f));
                        qv.y = pack_h2(fmaxf(acc[mt][j][2]+bE0, 0.f),
                                       fmaxf(acc[mt][j][3]+bE1, 0.f));
                        qv.z = pack_h2(fmaxf(acc[mt][j+1][0]+bO0, 0.f),
                                       fmaxf(acc[mt][j+1][1]+bO1, 0.f));
                        qv.w = pack_h2(fmaxf(acc[mt][j+1][2]+bO0, 0.f),
                                       fmaxf(acc[mt][j+1][3]+bO1, 0.f));
                        frag4[(rb*16 + (ng*4 + jp))*32 + lane] = qv;
                    }
                }
            } else {
                // final layer: relu(acc+bias), row-reduce, SMEM colsum
                #pragma unroll
                for (int j = 0; j < 8; j++) {
                    int col = ng*64 + j*8 + 2*tig;
                    float b0 = biasS[2*HID + col], b1 = biasS[2*HID + col + 1];
                    float s0 = 0.f, s1 = 0.f;
                    #pragma unroll
                    for (int mt = 0; mt < 2; mt++) {
                        s0 += fmaxf(acc[mt][j][0] + b0, 0.f)
                            + fmaxf(acc[mt][j][2] + b0, 0.f);
                        s1 += fmaxf(acc[mt][j][1] + b1, 0.f)
                            + fmaxf(acc[mt][j][3] + b1, 0.f);
                    }
                    #pragma unroll
                    for (int off = 4; off < 32; off <<= 1) {
                        s0 += __shfl_xor_sync(0xFFFFFFFFu, s0, off);
                        s1 += __shfl_xor_sync(0xFFFFFFFFu, s1, off);
                    }
                    if (lane < 4) {
                        atomicAdd(&colsum[col],     s0);
                        atomicAdd(&colsum[col + 1], s1);
                    }
                }
            }
        }
    }

    __syncthreads();
    if (tid < HID) atomicAdd(&gsum[b*HID + tid], colsum[tid]);
}

// ---------------------------------------------------------------------------
// Launch #7: f_phi
// ---------------------------------------------------------------------------
__global__ void fphi_kernel(const float* __restrict__ gsum,
                            const float* __restrict__ fw1, const float* __restrict__ fb1,
                            const float* __restrict__ fw2, const float* __restrict__ fb2,
                            const float* __restrict__ fw3, const float* __restrict__ fb3,
                            float* __restrict__ out) {
    __shared__ float ga[HID], gb[HID];
    int b = blockIdx.x, tid = threadIdx.x;
    ga[tid] = gsum[b*HID + tid] * (1.0f / (NN*NN));
    __syncthreads();
    float acc = fb1[tid];
    for (int f = 0; f < HID; f++) acc += ga[f] * fw1[f*HID + tid];
    gb[tid] = fmaxf(acc, 0.f);
    __syncthreads();
    acc = fb2[tid];
    for (int f = 0; f < HID; f++) acc += gb[f] * fw2[f*HID + tid];
    ga[tid] = fmaxf(acc, 0.f);
    __syncthreads();
    if (tid < AD) {
        float o = fb3[tid];
        for (int f = 0; f < HID; f++) o += ga[f] * fw3[f*AD + tid];
        out[b*AD + tid] = o;
    }
}

// ---------------------------------------------------------------------------
// Launch
// ---------------------------------------------------------------------------
extern "C" void kernel_launch(void* const* d_in, const int* in_sizes, int n_in,
                              void* d_out, int out_size) {
    (void)in_sizes; (void)n_in; (void)out_size;
    const float* img = (const float*)d_in[0];
    const float* q   = (const float*)d_in[1];
    const float* cw[4] = {(const float*)d_in[2],  (const float*)d_in[6],
                          (const float*)d_in[10], (const float*)d_in[14]};
    const float* cb[4] = {(const float*)d_in[3],  (const float*)d_in[7],
                          (const float*)d_in[11], (const float*)d_in[15]};
    const float* bg[4] = {(const float*)d_in[4],  (const float*)d_in[8],
                          (const float*)d_in[12], (const float*)d_in[16]};
    const float* bb[4] = {(const float*)d_in[5],  (const float*)d_in[9],
                          (const float*)d_in[13], (const float*)d_in[17]};
    const float* gw1 = (const float*)d_in[18]; const float* gb1 = (const float*)d_in[19];
    const float* gw2 = (const float*)d_in[20]; const float* gb2 = (const float*)d_in[21];
    const float* gw3 = (const float*)d_in[22]; const float* gb3 = (const float*)d_in[23];
    const float* gw4 = (const float*)d_in[24]; const float* gb4 = (const float*)d_in[25];
    const float* fw1 = (const float*)d_in[26]; const float* fb1 = (const float*)d_in[27];
    const float* fw2 = (const float*)d_in[28]; const float* fb2 = (const float*)d_in[29];
    const float* fw3 = (const float*)d_in[30]; const float* fb3 = (const float*)d_in[31];
    float* out = (float*)d_out;

    float *x1, *x2, *x3, *x4, *gsum, *bnsum, *bnsq;
    uint2* wfp;
    cudaGetSymbolAddress((void**)&x1,    g_x1);
    cudaGetSymbolAddress((void**)&x2,    g_x2);
    cudaGetSymbolAddress((void**)&x3,    g_x3);
    cudaGetSymbolAddress((void**)&x4,    g_x4);
    cudaGetSymbolAddress((void**)&gsum,  g_gsum);
    cudaGetSymbolAddress((void**)&wfp,   g_wf);
    cudaGetSymbolAddress((void**)&bnsum, g_bnsum);
    cudaGetSymbolAddress((void**)&bnsq,  g_bnsq);

    cudaFuncSetAttribute(rn_mma_kernel,
                         cudaFuncAttributeMaxDynamicSharedMemorySize, DYN_RN);

    // #1
    wfrag_zero_kernel<<<192, 256>>>(gw2, gw3, gw4, wfp, gsum, bnsum, bnsq);
    // #2
    conv_bn_kernel<3,24,128,64,0,false><<<BSZ*CH*64*64/256, 256>>>(
        img, cw[0], cb[0], nullptr, nullptr, nullptr, nullptr,
        x1, bnsum+0, bnsq+0);
    // #3 (finalizes BN1 inline)
    conv_bn_kernel<24,24,64,32,64*64,true><<<BSZ*CH*32*32/256, 256>>>(
        x1, cw[1], cb[1], bnsum+0, bnsq+0, bg[0], bb[0],
        x2, bnsum+CH, bnsq+CH);
    // #4
    conv_bn_kernel<24,24,32,16,32*32,true><<<BSZ*CH*16*16/256, 256>>>(
        x2, cw[2], cb[2], bnsum+CH, bnsq+CH, bg[1], bb[1],
        x3, bnsum+2*CH, bnsq+2*CH);
    // #5
    conv_bn_kernel<24,24,16,8,16*16,true><<<BSZ*CH*8*8/256, 256>>>(
        x3, cw[3], cb[3], bnsum+2*CH, bnsq+2*CH, bg[2], bb[2],
        x4, bnsum+3*CH, bnsq+3*CH);
    // #6 — the core (profiled by ncu -s 5 -c 1)
    rn_mma_kernel<<<BSZ*NN/2, 512, DYN_RN>>>(
        x4, q, bnsum+3*CH, bnsq+3*CH, bg[3], bb[3],
        gw1, gb1, gsum, wfp, gb2, gb3, gb4);
    // #7
    fphi_kernel<<<BSZ, 256>>>(gsum, fw1, fb1, fw2, fb2, fw3, fb3, out);
}

// round 7
// speedup vs baseline: 1.2631x; 1.2631x over previous
#include <cuda_runtime.h>
#include <cuda_fp16.h>
#include <math.h>
#include <stdint.h>

// ---------------------------------------------------------------------------
// Problem constants
// ---------------------------------------------------------------------------
#define BSZ   64
#define IMG   128
#define CH    24
#define QD    11
#define AD    10
#define NN    64      // objects per image (8x8)
#define FD    26      // CH + 2 coords
#define HID   256
#define EPSV  1e-5f

// rn_mma geometry (fp16) — Round-4 proven configuration
#define M_CTA     128
#define SA        264            // half-element stride
#define WSLAB_B   32768          // 4 k16-steps of fragment-ordered fp16 weights
#define N_SLABS   12             // 3 layers x 4 slabs
#define DYN_RN    (2*WSLAB_B + M_CTA*SA*2)   // 133120

// ---------------------------------------------------------------------------
// Scratch
// ---------------------------------------------------------------------------
__device__ float  g_x1[BSZ*CH*64*64];
__device__ float  g_x2[BSZ*CH*32*32];
__device__ float  g_x3[BSZ*CH*16*16];
__device__ float  g_x4[BSZ*CH*8*8];
__device__ float  g_u [BSZ*NN*HID];
__device__ float  g_v [BSZ*NN*HID];
__device__ float  g_s [BSZ*HID];
__device__ float  g_gsum[BSZ*HID];
__device__ uint2  g_wf[3*16*32*32];
__device__ float  g_bnsum[4*CH];
__device__ float  g_bnsq [4*CH];

// ---------------------------------------------------------------------------
// Helpers
// ---------------------------------------------------------------------------
__device__ __forceinline__ uint32_t smem_u32(const void* p) {
    uint32_t a;
    asm("{ .reg .u64 t; cvta.to.shared.u64 t, %1; cvt.u32.u64 %0, t; }"
        : "=r"(a) : "l"(p));
    return a;
}
__device__ __forceinline__ void mma_f16(float* c, const uint32_t* a,
                                        uint32_t b0, uint32_t b1) {
    asm volatile(
        "mma.sync.aligned.m16n8k16.row.col.f32.f16.f16.f32 "
        "{%0,%1,%2,%3}, {%4,%5,%6,%7}, {%8,%9}, {%0,%1,%2,%3};"
        : "+f"(c[0]), "+f"(c[1]), "+f"(c[2]), "+f"(c[3])
        : "r"(a[0]), "r"(a[1]), "r"(a[2]), "r"(a[3]), "r"(b0), "r"(b1));
}
__device__ __forceinline__ void cp16(uint32_t dst, const void* src) {
    asm volatile("cp.async.cg.shared.global [%0], [%1], 16;"
                 :: "r"(dst), "l"(__cvta_generic_to_global(src)) : "memory");
}
#define CP_COMMIT() asm volatile("cp.async.commit_group;" ::: "memory")
#define CP_WAIT1()  asm volatile("cp.async.wait_group 1;" ::: "memory")
#define CP_WAIT0()  asm volatile("cp.async.wait_group 0;" ::: "memory")

__device__ __forceinline__ uint32_t pack_h2(float lo, float hi) {
    __half2 h = __floats2half2_rn(lo, hi);
    return *(uint32_t*)&h;
}

// ---------------------------------------------------------------------------
// Launch #1: fragment-ordered fp16 weights + zero accumulators
// ---------------------------------------------------------------------------
__global__ void wfrag_zero_kernel(const float* __restrict__ gw2,
                                  const float* __restrict__ gw3,
                                  const float* __restrict__ gw4,
                                  uint2* __restrict__ wf,
                                  float* __restrict__ gsum,
                                  float* __restrict__ bnsum,
                                  float* __restrict__ bnsq) {
    int idx = blockIdx.x * blockDim.x + threadIdx.x;
    if (idx < BSZ*HID) gsum[idx] = 0.f;
    if (idx < 4*CH) { bnsum[idx] = 0.f; bnsq[idx] = 0.f; }
    if (idx >= 3*16384) return;
    int l  = idx >> 14;
    int r  = idx & 16383;
    int k  = r >> 10;
    int jg = (r >> 5) & 31;
    int t  = r & 31;
    const float* g = (l == 0) ? gw2 : (l == 1) ? gw3 : gw4;
    int n  = jg*8 + (t >> 2);
    int kk = k*16 + 2*(t & 3);
    uint2 val;
    val.x = pack_h2(g[(size_t)kk*HID + n],     g[(size_t)(kk+1)*HID + n]);
    val.y = pack_h2(g[(size_t)(kk+8)*HID + n], g[(size_t)(kk+9)*HID + n]);
    wf[idx] = val;
}

// ---------------------------------------------------------------------------
// Launches #2-5: tiled conv (k=3,s=2,p=1) + inline input-BN finalize+apply
//                + bias + ReLU + output channel stats.
// One CTA = (image, TILE x TILE output tile). Input channel planes staged in
// double-buffered SMEM; weights re-laid [ci][co][12] for LDS.128; each thread
// accumulates ALL CO output channels for one pixel in registers.
// ---------------------------------------------------------------------------
template<int CI, int CO, int HIN, int HOUT, int TILE, int HW_IN, bool APPLY>
__global__ void conv_tile_kernel(const float* __restrict__ in,
                                 const float* __restrict__ w,
                                 const float* __restrict__ bias,
                                 const float* __restrict__ sum_in,
                                 const float* __restrict__ sq_in,
                                 const float* __restrict__ bg_in,
                                 const float* __restrict__ bb_in,
                                 float* __restrict__ out,
                                 float* __restrict__ sum_g,
                                 float* __restrict__ sq_g) {
    constexpr int PW  = 2*TILE + 1;
    constexpr int PSZ = PW*PW;
    constexpr int NT  = TILE*TILE;
    __shared__ float wS[CI*CO*12];
    __shared__ float bS[CO];
    __shared__ float planes[2][PSZ];
    __shared__ float sci[CI], shi[CI];
    __shared__ float csum[CO], csq[CO];

    const int tid = threadIdx.x;
    // weight re-layout: wS[(ci*CO+co)*12 + k] = w[(co*CI+ci)*9 + k]
    for (int i = tid; i < CI*CO*9; i += NT) {
        int cico = i / 9, k = i - cico*9;
        int co = cico / CI, ci = cico - co*CI;
        wS[(ci*CO + co)*12 + k] = w[i];
    }
    if (tid < CO) { bS[tid] = bias[tid]; csum[tid] = 0.f; csq[tid] = 0.f; }
    if (tid < CI) {
        if (APPLY) {
            float cnt = (float)(BSZ * HW_IN);
            float m   = sum_in[tid] / cnt;
            float var = sq_in[tid] / cnt - m * m;
            float inv = rsqrtf(var + EPSV);
            float sc  = bg_in[tid] * inv;
            sci[tid] = sc;
            shi[tid] = bb_in[tid] - m * sc;
        } else { sci[tid] = 1.f; shi[tid] = 0.f; }
    }
    __syncthreads();

    constexpr int TPS = HOUT / TILE;     // tiles per side
    const int bx = blockIdx.x;
    const int b  = bx / (TPS*TPS);
    const int tr = bx - b*(TPS*TPS);
    const int ty = (tr / TPS) * TILE;
    const int tx = (tr - (tr / TPS)*TPS) * TILE;
    const int py = tid / TILE;
    const int px = tid - py*TILE;
    const int iy0 = ty*2 - 1;
    const int ix0 = tx*2 - 1;

    auto load_plane = [&](int ci, int buf) {
        const float* ip = in + ((size_t)(b*CI + ci) * HIN) * HIN;
        float sc = sci[ci], sh = shi[ci];
        #pragma unroll
        for (int i = tid; i < PSZ; i += NT) {
            int ry = i / PW, rx = i - ry*PW;
            int gy = iy0 + ry, gx = ix0 + rx;
            float v = 0.f;
            if (gy >= 0 && gy < HIN && gx >= 0 && gx < HIN)
                v = ip[gy*HIN + gx] * sc + sh;
            planes[buf][i] = v;
        }
    };

    float acc[CO];
    #pragma unroll
    for (int co = 0; co < CO; co++) acc[co] = 0.f;

    load_plane(0, 0);
    __syncthreads();
    #pragma unroll 1
    for (int ci = 0; ci < CI; ci++) {
        if (ci + 1 < CI) load_plane(ci + 1, (ci + 1) & 1);
        const float* pl = planes[ci & 1];
        float win[9];
        #pragma unroll
        for (int dy = 0; dy < 3; dy++)
            #pragma unroll
            for (int dx = 0; dx < 3; dx++)
                win[dy*3+dx] = pl[(2*py + dy)*PW + 2*px + dx];
        #pragma unroll
        for (int co = 0; co < CO; co++) {
            const float4 w0 = *(const float4*)&wS[(ci*CO + co)*12];
            const float4 w1 = *(const float4*)&wS[(ci*CO + co)*12 + 4];
            const float  w8 = wS[(ci*CO + co)*12 + 8];
            acc[co] += win[0]*w0.x + win[1]*w0.y + win[2]*w0.z
                     + win[3]*w0.w + win[4]*w1.x + win[5]*w1.y
                     + win[6]*w1.z + win[7]*w1.w + win[8]*w8;
        }
        __syncthreads();
    }

    // epilogue: bias + relu + store + channel stats
    const int lane = tid & 31;
    #pragma unroll
    for (int co = 0; co < CO; co++) {
        float val = fmaxf(acc[co] + bS[co], 0.f);
        out[((size_t)(b*CO + co)*HOUT + ty + py)*HOUT + tx + px] = val;
        float s = val, s2 = val*val;
        #pragma unroll
        for (int off = 16; off > 0; off >>= 1) {
            s  += __shfl_xor_sync(0xFFFFFFFFu, s,  off);
            s2 += __shfl_xor_sync(0xFFFFFFFFu, s2, off);
        }
        if (lane == 0) { atomicAdd(&csum[co], s); atomicAdd(&csq[co], s2); }
    }
    __syncthreads();
    if (tid < CO) {
        atomicAdd(&sum_g[tid], csum[tid]);
        atomicAdd(&sq_g [tid], csq [tid]);
    }
}

// ---------------------------------------------------------------------------
// Launch #6: layer-1 factorization (u, v) with inline BN4 finalize;
//            blocks with n==0 also compute s for their image.
// ---------------------------------------------------------------------------
__global__ void uv_kernel(const float* __restrict__ x4,
                          const float* __restrict__ bnsum4,
                          const float* __restrict__ bnsq4,
                          const float* __restrict__ bg4,
                          const float* __restrict__ bb4,
                          const float* __restrict__ q,
                          const float* __restrict__ gw1,
                          const float* __restrict__ gb1,
                          float* __restrict__ u, float* __restrict__ v,
                          float* __restrict__ s) {
    __shared__ float o[FD];
    int bn = blockIdx.x;
    int b = bn >> 6, n = bn & 63;
    int tid = threadIdx.x;
    if (tid < CH) {
        float cnt = (float)(BSZ * 64);
        float m   = bnsum4[tid] / cnt;
        float var = bnsq4[tid] / cnt - m * m;
        float inv = rsqrtf(var + EPSV);
        float sc  = bg4[tid] * inv;
        float sh  = bb4[tid] - m * sc;
        o[tid] = x4[(size_t)(b*CH + tid)*64 + n] * sc + sh;
    } else if (tid == CH)     o[CH]   = (float)(n >> 3) * 0.125f;
    else if (tid == CH + 1)   o[CH+1] = (float)(n & 7)  * 0.125f;
    __syncthreads();
    float us = 0.f, vs = 0.f;
    #pragma unroll
    for (int f = 0; f < FD; f++) {
        float ov = o[f];
        us += ov * gw1[f*HID + tid];
        vs += ov * gw1[(FD + f)*HID + tid];
    }
    u[bn*HID + tid] = us;
    v[bn*HID + tid] = vs;

    if (n == 0) {
        __shared__ float qv[QD];
        if (tid < QD) qv[tid] = q[b*QD + tid];
        __syncthreads();
        float sa = gb1[tid];
        #pragma unroll
        for (int t = 0; t < QD; t++)
            sa += qv[t] * gw1[(2*FD + t)*HID + tid];
        s[b*HID + tid] = sa;
    }
}

// ---------------------------------------------------------------------------
// Launch #7: tensor-core relational core (Round-4 proven version).
// ---------------------------------------------------------------------------
__global__ void __launch_bounds__(512, 1)
rn_mma_kernel(const float* __restrict__ u, const float* __restrict__ v,
              const float* __restrict__ sb, float* __restrict__ gsum,
              const uint2* __restrict__ wf,
              const float* __restrict__ gb2, const float* __restrict__ gb3,
              const float* __restrict__ gb4) {
    extern __shared__ char dyn[];
    __half* hAh = (__half*)(dyn + 2*WSLAB_B);
    const uint2* wbuf2 = (const uint2*)dyn;
    const uint32_t wsm = smem_u32(dyn);
    __shared__ float biasS[3*HID];
    __shared__ float colsum[HID];

    const int tid  = threadIdx.x;
    const int lane = tid & 31;
    const int warp = tid >> 5;
    const int mg   = warp & 3;
    const int ng   = warp >> 2;
    const int tig  = lane & 3;

    for (int i = tid; i < HID; i += 512) {
        biasS[i]         = gb2[i];
        biasS[HID + i]   = gb3[i];
        biasS[2*HID + i] = gb4[i];
    }
    if (tid < HID) colsum[tid] = 0.f;

    const int b  = blockIdx.x >> 5;
    const int i0 = (blockIdx.x & 31) * 2;
    {
        const int row = tid >> 2;
        const int c0  = (tid & 3) * 64;
        const int ii  = i0 + (row >> 6);
        const int jj  = row & 63;
        const float* up = u  + (size_t)(b*NN + ii) * HID;
        const float* vp = v  + (size_t)(b*NN + jj) * HID;
        const float* sp = sb + (size_t)b * HID;
        #pragma unroll
        for (int f = 0; f < 8; f++) {
            int c = c0 + f*8;
            float4 u0 = *(const float4*)(up + c);
            float4 v0 = *(const float4*)(vp + c);
            float4 s0 = *(const float4*)(sp + c);
            float4 u1 = *(const float4*)(up + c + 4);
            float4 v1 = *(const float4*)(vp + c + 4);
            float4 s1 = *(const float4*)(sp + c + 4);
            uint4 hq;
            hq.x = pack_h2(fmaxf(u0.x+v0.x+s0.x, 0.f), fmaxf(u0.y+v0.y+s0.y, 0.f));
            hq.y = pack_h2(fmaxf(u0.z+v0.z+s0.z, 0.f), fmaxf(u0.w+v0.w+s0.w, 0.f));
            hq.z = pack_h2(fmaxf(u1.x+v1.x+s1.x, 0.f), fmaxf(u1.y+v1.y+s1.y, 0.f));
            hq.w = pack_h2(fmaxf(u1.z+v1.z+s1.z, 0.f), fmaxf(u1.w+v1.w+s1.w, 0.f));
            *(uint4*)(hAh + row*SA + c) = hq;
        }
    }

    {
        const char* src = (const char*)wf;
        #pragma unroll
        for (int i = 0; i < 4; i++)
            cp16(wsm + (i*512 + tid)*16, src + (i*512 + tid)*16);
        CP_COMMIT();
    }

    float acc[2][8][4];

    #pragma unroll 1
    for (int sl = 0; sl < N_SLABS; sl++) {
        const int l   = sl >> 2;
        const int cur = sl & 1;
        __syncthreads();
        if (sl + 1 < N_SLABS) {
            const char* src = (const char*)wf + (size_t)(sl + 1) * WSLAB_B;
            uint32_t dst = wsm + (cur ^ 1) * WSLAB_B;
            #pragma unroll
            for (int i = 0; i < 4; i++)
                cp16(dst + (i*512 + tid)*16, src + (i*512 + tid)*16);
            CP_COMMIT();
            CP_WAIT1();
        } else {
            CP_WAIT0();
        }
        __syncthreads();

        if ((sl & 3) == 0) {
            #pragma unroll
            for (int mt = 0; mt < 2; mt++)
                #pragma unroll
                for (int j = 0; j < 8; j++)
                    #pragma unroll
                    for (int c = 0; c < 4; c++)
                        acc[mt][j][c] = 0.f;
        }

        const uint2* wslab = wbuf2 + cur * (WSLAB_B/8);
        const int kbase = (sl & 3) * 4;
        #pragma unroll
        for (int kk = 0; kk < 4; kk++) {
            const int kcol = (kbase + kk) * 16;
            uint32_t a[2][4];
            #pragma unroll
            for (int mt = 0; mt < 2; mt++) {
                int rA = mg*32 + mt*16 + (lane >> 2);
                const __half* base = hAh + rA*SA + kcol + 2*tig;
                a[mt][0] = *(const uint32_t*)(base);
                a[mt][1] = *(const uint32_t*)(base + 8*SA);
                a[mt][2] = *(const uint32_t*)(base + 8);
                a[mt][3] = *(const uint32_t*)(base + 8*SA + 8);
            }
            #pragma unroll
            for (int j = 0; j < 8; j++) {
                uint2 bb = wslab[(kk*32 + (ng*8 + j))*32 + lane];
                mma_f16(acc[0][j], a[0], bb.x, bb.y);
                mma_f16(acc[1][j], a[1], bb.x, bb.y);
            }
        }

        if ((sl & 3) == 3) {
            __syncthreads();
            if (l < 2) {
                const float* bl = biasS + l*HID;
                #pragma unroll
                for (int mt = 0; mt < 2; mt++) {
                    int rA = mg*32 + mt*16 + (lane >> 2);
                    #pragma unroll
                    for (int j = 0; j < 8; j++) {
                        int col = ng*64 + j*8 + 2*tig;
                        float b0 = bl[col], b1 = bl[col+1];
                        uint32_t lo = pack_h2(fmaxf(acc[mt][j][0] + b0, 0.f),
                                              fmaxf(acc[mt][j][1] + b1, 0.f));
                        uint32_t hi = pack_h2(fmaxf(acc[mt][j][2] + b0, 0.f),
                                              fmaxf(acc[mt][j][3] + b1, 0.f));
                        *(uint32_t*)(hAh + rA*SA + col)     = lo;
                        *(uint32_t*)(hAh + (rA+8)*SA + col) = hi;
                    }
                }
                __syncthreads();
            } else {
                const float* bl = biasS + 2*HID;
                #pragma unroll
                for (int j = 0; j < 8; j++) {
                    int col = ng*64 + j*8 + 2*tig;
                    float b0 = bl[col], b1 = bl[col+1];
                    float s0 = 0.f, s1 = 0.f;
                    #pragma unroll
                    for (int mt = 0; mt < 2; mt++) {
                        s0 += fmaxf(acc[mt][j][0] + b0, 0.f)
                            + fmaxf(acc[mt][j][2] + b0, 0.f);
                        s1 += fmaxf(acc[mt][j][1] + b1, 0.f)
                            + fmaxf(acc[mt][j][3] + b1, 0.f);
                    }
                    #pragma unroll
                    for (int off = 4; off < 32; off <<= 1) {
                        s0 += __shfl_xor_sync(0xFFFFFFFFu, s0, off);
                        s1 += __shfl_xor_sync(0xFFFFFFFFu, s1, off);
                    }
                    if (lane < 4) {
                        atomicAdd(&colsum[col],     s0);
                        atomicAdd(&colsum[col + 1], s1);
                    }
                }
            }
        }
    }

    __syncthreads();
    if (tid < HID) atomicAdd(&gsum[b*HID + tid], colsum[tid]);
}

// ---------------------------------------------------------------------------
// Launch #8: f_phi
// ---------------------------------------------------------------------------
__global__ void fphi_kernel(const float* __restrict__ gsum,
                            const float* __restrict__ fw1, const float* __restrict__ fb1,
                            const float* __restrict__ fw2, const float* __restrict__ fb2,
                            const float* __restrict__ fw3, const float* __restrict__ fb3,
                            float* __restrict__ out) {
    __shared__ float ga[HID], gb[HID];
    int b = blockIdx.x, tid = threadIdx.x;
    ga[tid] = gsum[b*HID + tid] * (1.0f / (NN*NN));
    __syncthreads();
    float acc = fb1[tid];
    for (int f = 0; f < HID; f++) acc += ga[f] * fw1[f*HID + tid];
    gb[tid] = fmaxf(acc, 0.f);
    __syncthreads();
    acc = fb2[tid];
    for (int f = 0; f < HID; f++) acc += gb[f] * fw2[f*HID + tid];
    ga[tid] = fmaxf(acc, 0.f);
    __syncthreads();
    if (tid < AD) {
        float o = fb3[tid];
        for (int f = 0; f < HID; f++) o += ga[f] * fw3[f*AD + tid];
        out[b*AD + tid] = o;
    }
}

// ---------------------------------------------------------------------------
// Launch
// ---------------------------------------------------------------------------
extern "C" void kernel_launch(void* const* d_in, const int* in_sizes, int n_in,
                              void* d_out, int out_size) {
    (void)in_sizes; (void)n_in; (void)out_size;
    const float* img = (const float*)d_in[0];
    const float* q   = (const float*)d_in[1];
    const float* cw[4] = {(const float*)d_in[2],  (const float*)d_in[6],
                          (const float*)d_in[10], (const float*)d_in[14]};
    const float* cb[4] = {(const float*)d_in[3],  (const float*)d_in[7],
                          (const float*)d_in[11], (const float*)d_in[15]};
    const float* bg[4] = {(const float*)d_in[4],  (const float*)d_in[8],
                          (const float*)d_in[12], (const float*)d_in[16]};
    const float* bb[4] = {(const float*)d_in[5],  (const float*)d_in[9],
                          (const float*)d_in[13], (const float*)d_in[17]};
    const float* gw1 = (const float*)d_in[18]; const float* gb1 = (const float*)d_in[19];
    const float* gw2 = (const float*)d_in[20]; const float* gb2 = (const float*)d_in[21];
    const float* gw3 = (const float*)d_in[22]; const float* gb3 = (const float*)d_in[23];
    const float* gw4 = (const float*)d_in[24]; const float* gb4 = (const float*)d_in[25];
    const float* fw1 = (const float*)d_in[26]; const float* fb1 = (const float*)d_in[27];
    const float* fw2 = (const float*)d_in[28]; const float* fb2 = (const float*)d_in[29];
    const float* fw3 = (const float*)d_in[30]; const float* fb3 = (const float*)d_in[31];
    float* out = (float*)d_out;

    float *x1, *x2, *x3, *x4, *u, *v, *s, *gsum, *bnsum, *bnsq;
    uint2* wfp;
    cudaGetSymbolAddress((void**)&x1,    g_x1);
    cudaGetSymbolAddress((void**)&x2,    g_x2);
    cudaGetSymbolAddress((void**)&x3,    g_x3);
    cudaGetSymbolAddress((void**)&x4,    g_x4);
    cudaGetSymbolAddress((void**)&u,     g_u);
    cudaGetSymbolAddress((void**)&v,     g_v);
    cudaGetSymbolAddress((void**)&s,     g_s);
    cudaGetSymbolAddress((void**)&gsum,  g_gsum);
    cudaGetSymbolAddress((void**)&wfp,   g_wf);
    cudaGetSymbolAddress((void**)&bnsum, g_bnsum);
    cudaGetSymbolAddress((void**)&bnsq,  g_bnsq);

    cudaFuncSetAttribute(rn_mma_kernel,
                         cudaFuncAttributeMaxDynamicSharedMemorySize, DYN_RN);

    // #1
    wfrag_zero_kernel<<<192, 256>>>(gw2, gw3, gw4, wfp, gsum, bnsum, bnsq);
    // #2: conv1 128->64, 4x4 tiles of 16
    conv_tile_kernel<3,24,128,64,16,0,false><<<BSZ*16, 256>>>(
        img, cw[0], cb[0], nullptr, nullptr, nullptr, nullptr,
        x1, bnsum+0, bnsq+0);
    // #3: conv2 64->32 (finalizes+applies BN1 inline)
    conv_tile_kernel<24,24,64,32,16,64*64,true><<<BSZ*4, 256>>>(
        x1, cw[1], cb[1], bnsum+0, bnsq+0, bg[0], bb[0],
        x2, bnsum+CH, bnsq+CH);
    // #4: conv3 32->16
    conv_tile_kernel<24,24,32,16,16,32*32,true><<<BSZ, 256>>>(
        x2, cw[2], cb[2], bnsum+CH, bnsq+CH, bg[1], bb[1],
        x3, bnsum+2*CH, bnsq+2*CH);
    // #5: conv4 16->8 (TILE=8, 64 threads)
    conv_tile_kernel<24,24,16,8,8,16*16,true><<<BSZ, 64>>>(
        x3, cw[3], cb[3], bnsum+2*CH, bnsq+2*CH, bg[2], bb[2],
        x4, bnsum+3*CH, bnsq+3*CH);
    // #6: u/v (+s for n==0 blocks), BN4 finalize inline
    uv_kernel<<<BSZ*NN, 256>>>(x4, bnsum+3*CH, bnsq+3*CH, bg[3], bb[3],
                               q, gw1, gb1, u, v, s);
    // #7: the core
    rn_mma_kernel<<<BSZ*NN/2, 512, DYN_RN>>>(u, v, s, gsum, wfp, gb2, gb3, gb4);
    // #8
    fphi_kernel<<<BSZ, 256>>>(gsum, fw1, fb1, fw2, fb2, fw3, fb3, out);
}

// round 10
// speedup vs baseline: 1.3903x; 1.1007x over previous
#include <cuda_runtime.h>
#include <cuda_fp16.h>
#include <math.h>
#include <stdint.h>

// ---------------------------------------------------------------------------
// Problem constants
// ---------------------------------------------------------------------------
#define BSZ   64
#define IMG   128
#define CH    24
#define QD    11
#define AD    10
#define NN    64      // objects per image (8x8)
#define FD    26      // CH + 2 coords
#define HID   256
#define EPSV  1e-5f

// rn_mma geometry (fp16) — proven configuration
#define M_CTA     128
#define SA        264            // half-element stride
#define WSLAB_B   32768
#define N_SLABS   12
#define DYN_RN    (2*WSLAB_B + M_CTA*SA*2)   // 133120

// ---------------------------------------------------------------------------
// Scratch
// ---------------------------------------------------------------------------
__device__ float  g_x1[BSZ*CH*64*64];
__device__ float  g_x2[BSZ*CH*32*32];
__device__ float  g_x3[BSZ*CH*16*16];
__device__ float  g_x4[BSZ*CH*8*8];
__device__ float  g_u [BSZ*NN*HID];
__device__ float  g_v [BSZ*NN*HID];
__device__ float  g_s [BSZ*HID];
__device__ float  g_gsum[BSZ*HID];    // zero-init at load; re-zeroed by fphi
__device__ uint2  g_wf[3*16*32*32];
__device__ float  g_bnsum[4*CH];      // zero-init at load; re-zeroed by fphi
__device__ float  g_bnsq [4*CH];

// ---------------------------------------------------------------------------
// Helpers
// ---------------------------------------------------------------------------
__device__ __forceinline__ uint32_t smem_u32(const void* p) {
    uint32_t a;
    asm("{ .reg .u64 t; cvta.to.shared.u64 t, %1; cvt.u32.u64 %0, t; }"
        : "=r"(a) : "l"(p));
    return a;
}
__device__ __forceinline__ void mma_f16(float* c, const uint32_t* a,
                                        uint32_t b0, uint32_t b1) {
    asm volatile(
        "mma.sync.aligned.m16n8k16.row.col.f32.f16.f16.f32 "
        "{%0,%1,%2,%3}, {%4,%5,%6,%7}, {%8,%9}, {%0,%1,%2,%3};"
        : "+f"(c[0]), "+f"(c[1]), "+f"(c[2]), "+f"(c[3])
        : "r"(a[0]), "r"(a[1]), "r"(a[2]), "r"(a[3]), "r"(b0), "r"(b1));
}
__device__ __forceinline__ void cp16(uint32_t dst, const void* src) {
    asm volatile("cp.async.cg.shared.global [%0], [%1], 16;"
                 :: "r"(dst), "l"(__cvta_generic_to_global(src)) : "memory");
}
#define CP_COMMIT() asm volatile("cp.async.commit_group;" ::: "memory")
#define CP_WAIT1()  asm volatile("cp.async.wait_group 1;" ::: "memory")
#define CP_WAIT0()  asm volatile("cp.async.wait_group 0;" ::: "memory")

__device__ __forceinline__ uint32_t pack_h2(float lo, float hi) {
    __half2 h = __floats2half2_rn(lo, hi);
    return *(uint32_t*)&h;
}

// ---------------------------------------------------------------------------
// Tiled conv (k=3,s=2,p=1) + inline input-BN + bias + ReLU + channel stats.
// ALL big buffers in DYNAMIC smem (planes, then weights at aligned offset);
// static smem stays tiny so static+dynamic accounting is governed purely by
// the cudaFuncSetAttribute opt-in (the rn_mma-proven pattern).
// dyn smem bytes = (PL_PAD + CI*CO*12) * 4
// ---------------------------------------------------------------------------
template<int CI, int CO, int HIN, int HOUT, int TILE, int CPG, int HW_IN,
         bool APPLY, bool WFRAG>
__global__ void __launch_bounds__(TILE*TILE*CO/CPG)
conv_tile_kernel(const float* __restrict__ in,
                 const float* __restrict__ w,
                 const float* __restrict__ bias,
                 const float* __restrict__ sum_in,
                 const float* __restrict__ sq_in,
                 const float* __restrict__ bg_in,
                 const float* __restrict__ bb_in,
                 float* __restrict__ out,
                 float* __restrict__ sum_g,
                 float* __restrict__ sq_g,
                 const float* __restrict__ gw2,
                 const float* __restrict__ gw3,
                 const float* __restrict__ gw4,
                 uint2* __restrict__ wf) {
    constexpr int PW     = 2*TILE + 1;
    constexpr int PSZ    = PW*PW;
    constexpr int NPIX   = TILE*TILE;
    constexpr int NG     = CO/CPG;
    constexpr int NT     = NPIX*NG;
    constexpr int PL_PAD = (CI*PSZ + 3) & ~3;       // 16B-align weight region
    extern __shared__ float plS[];                   // planes + weights
    float* wS = plS + PL_PAD;                        // CI*CO*12 floats
    __shared__ float bS[CO];
    __shared__ float sci[CI], shi[CI];
    __shared__ float csum[CO], csq[CO];

    const int tid = threadIdx.x;
    // weight re-layout: wS[(ci*CO+co)*12 + k] = w[(co*CI+ci)*9 + k]
    for (int i = tid; i < CI*CO*9; i += NT) {
        int cico = i / 9, k = i - cico*9;
        int co = cico / CI, ci = cico - co*CI;
        wS[(ci*CO + co)*12 + k] = w[i];
    }
    if (tid < CO) { bS[tid] = bias[tid]; csum[tid] = 0.f; csq[tid] = 0.f; }
    if (tid < CI) {
        if (APPLY) {
            float cnt = (float)(BSZ * HW_IN);
            float m   = sum_in[tid] / cnt;
            float var = sq_in[tid] / cnt - m * m;
            float inv = rsqrtf(var + EPSV);
            float sc  = bg_in[tid] * inv;
            sci[tid] = sc;
            shi[tid] = bb_in[tid] - m * sc;
        } else { sci[tid] = 1.f; shi[tid] = 0.f; }
    }
    __syncthreads();

    constexpr int TPS = HOUT / TILE;
    const int bx = blockIdx.x;
    const int b  = bx / (TPS*TPS);
    const int tr = bx - b*(TPS*TPS);
    const int ty = (tr / TPS) * TILE;
    const int tx = (tr - (tr / TPS)*TPS) * TILE;
    const int iy0 = ty*2 - 1;
    const int ix0 = tx*2 - 1;

    // stage all input planes (BN applied inline)
    for (int i = tid; i < CI*PSZ; i += NT) {
        int ci = i / PSZ;
        int r  = i - ci*PSZ;
        int ry = r / PW, rx = r - ry*PW;
        int gy = iy0 + ry, gx = ix0 + rx;
        float v = 0.f;
        if (gy >= 0 && gy < HIN && gx >= 0 && gx < HIN)
            v = in[((size_t)(b*CI + ci)*HIN + gy)*HIN + gx] * sci[ci] + shi[ci];
        plS[i] = v;
    }
    __syncthreads();

    const int pix = tid & (NPIX - 1);
    const int cg  = tid / NPIX;
    const int py  = pix / TILE;
    const int px  = pix - py*TILE;
    const int co0 = cg * CPG;

    float acc[CPG];
    #pragma unroll
    for (int cc = 0; cc < CPG; cc++) acc[cc] = 0.f;

    #pragma unroll 2
    for (int ci = 0; ci < CI; ci++) {
        const float* pl = plS + ci*PSZ + (2*py)*PW + 2*px;
        float win[9];
        #pragma unroll
        for (int dy = 0; dy < 3; dy++) {
            win[dy*3+0] = pl[dy*PW+0];
            win[dy*3+1] = pl[dy*PW+1];
            win[dy*3+2] = pl[dy*PW+2];
        }
        #pragma unroll
        for (int cc = 0; cc < CPG; cc++) {
            const float* wp = &wS[(ci*CO + co0 + cc)*12];
            const float4 w0 = *(const float4*)wp;
            const float4 w1 = *(const float4*)(wp + 4);
            const float  w8 = wp[8];
            acc[cc] += win[0]*w0.x + win[1]*w0.y + win[2]*w0.z
                     + win[3]*w0.w + win[4]*w1.x + win[5]*w1.y
                     + win[6]*w1.z + win[7]*w1.w + win[8]*w8;
        }
    }

    // epilogue: bias + relu + store + channel stats
    const int lane = tid & 31;
    #pragma unroll
    for (int cc = 0; cc < CPG; cc++) {
        int co = co0 + cc;
        float val = fmaxf(acc[cc] + bS[co], 0.f);
        out[((size_t)(b*CO + co)*HOUT + ty + py)*HOUT + tx + px] = val;
        float s = val, s2 = val*val;
        #pragma unroll
        for (int off = 16; off > 0; off >>= 1) {
            s  += __shfl_xor_sync(0xFFFFFFFFu, s,  off);
            s2 += __shfl_xor_sync(0xFFFFFFFFu, s2, off);
        }
        if (lane == 0) { atomicAdd(&csum[co], s); atomicAdd(&csq[co], s2); }
    }
    __syncthreads();
    if (tid < CO) {
        atomicAdd(&sum_g[tid], csum[tid]);
        atomicAdd(&sq_g [tid], csq [tid]);
    }

    if (WFRAG) {
        // fragment-ordered fp16 g_theta weights (one item per thread)
        int gidx = blockIdx.x * NT + tid;
        if (gidx < 3*16384) {
            int l  = gidx >> 14;
            int r  = gidx & 16383;
            int k  = r >> 10;
            int jg = (r >> 5) & 31;
            int t  = r & 31;
            const float* g = (l == 0) ? gw2 : (l == 1) ? gw3 : gw4;
            int n  = jg*8 + (t >> 2);
            int kk = k*16 + 2*(t & 3);
            uint2 val;
            val.x = pack_h2(g[(size_t)kk*HID + n],     g[(size_t)(kk+1)*HID + n]);
            val.y = pack_h2(g[(size_t)(kk+8)*HID + n], g[(size_t)(kk+9)*HID + n]);
            wf[gidx] = val;
        }
    }
}

// dynamic smem sizes per instantiation
#define CONV1_DYN ((((3*33*33 + 3) & ~3) + 3*24*12) * 4)     // 16528
#define CONVN_DYN ((((24*17*17 + 3) & ~3) + 24*24*12) * 4)   // 55392

// ---------------------------------------------------------------------------
// Launch #5: layer-1 factorization (u, v) with inline BN4 finalize;
//            blocks with n==0 also compute s for their image.
// ---------------------------------------------------------------------------
__global__ void uv_kernel(const float* __restrict__ x4,
                          const float* __restrict__ bnsum4,
                          const float* __restrict__ bnsq4,
                          const float* __restrict__ bg4,
                          const float* __restrict__ bb4,
                          const float* __restrict__ q,
                          const float* __restrict__ gw1,
                          const float* __restrict__ gb1,
                          float* __restrict__ u, float* __restrict__ v,
                          float* __restrict__ s) {
    __shared__ float o[FD];
    int bn = blockIdx.x;
    int b = bn >> 6, n = bn & 63;
    int tid = threadIdx.x;
    if (tid < CH) {
        float cnt = (float)(BSZ * 64);
        float m   = bnsum4[tid] / cnt;
        float var = bnsq4[tid] / cnt - m * m;
        float inv = rsqrtf(var + EPSV);
        float sc  = bg4[tid] * inv;
        float sh  = bb4[tid] - m * sc;
        o[tid] = x4[(size_t)(b*CH + tid)*64 + n] * sc + sh;
    } else if (tid == CH)     o[CH]   = (float)(n >> 3) * 0.125f;
    else if (tid == CH + 1)   o[CH+1] = (float)(n & 7)  * 0.125f;
    __syncthreads();
    float us = 0.f, vs = 0.f;
    #pragma unroll
    for (int f = 0; f < FD; f++) {
        float ov = o[f];
        us += ov * gw1[f*HID + tid];
        vs += ov * gw1[(FD + f)*HID + tid];
    }
    u[bn*HID + tid] = us;
    v[bn*HID + tid] = vs;

    if (n == 0) {
        __shared__ float qv[QD];
        if (tid < QD) qv[tid] = q[b*QD + tid];
        __syncthreads();
        float sa = gb1[tid];
        #pragma unroll
        for (int t = 0; t < QD; t++)
            sa += qv[t] * gw1[(2*FD + t)*HID + tid];
        s[b*HID + tid] = sa;
    }
}

// ---------------------------------------------------------------------------
// Launch #6: tensor-core relational core (proven fp16 version).
// ---------------------------------------------------------------------------
__global__ void __launch_bounds__(512, 1)
rn_mma_kernel(const float* __restrict__ u, const float* __restrict__ v,
              const float* __restrict__ sb, float* __restrict__ gsum,
              const uint2* __restrict__ wf,
              const float* __restrict__ gb2, const float* __restrict__ gb3,
              const float* __restrict__ gb4) {
    extern __shared__ char dyn[];
    __half* hAh = (__half*)(dyn + 2*WSLAB_B);
    const uint2* wbuf2 = (const uint2*)dyn;
    const uint32_t wsm = smem_u32(dyn);
    __shared__ float biasS[3*HID];
    __shared__ float colsum[HID];

    const int tid  = threadIdx.x;
    const int lane = tid & 31;
    const int warp = tid >> 5;
    const int mg   = warp & 3;
    const int ng   = warp >> 2;
    const int tig  = lane & 3;

    for (int i = tid; i < HID; i += 512) {
        biasS[i]         = gb2[i];
        biasS[HID + i]   = gb3[i];
        biasS[2*HID + i] = gb4[i];
    }
    if (tid < HID) colsum[tid] = 0.f;

    const int b  = blockIdx.x >> 5;
    const int i0 = (blockIdx.x & 31) * 2;
    {
        const int row = tid >> 2;
        const int c0  = (tid & 3) * 64;
        const int ii  = i0 + (row >> 6);
        const int jj  = row & 63;
        const float* up = u  + (size_t)(b*NN + ii) * HID;
        const float* vp = v  + (size_t)(b*NN + jj) * HID;
        const float* sp = sb + (size_t)b * HID;
        #pragma unroll
        for (int f = 0; f < 8; f++) {
            int c = c0 + f*8;
            float4 u0 = *(const float4*)(up + c);
            float4 v0 = *(const float4*)(vp + c);
            float4 s0 = *(const float4*)(sp + c);
            float4 u1 = *(const float4*)(up + c + 4);
            float4 v1 = *(const float4*)(vp + c + 4);
            float4 s1 = *(const float4*)(sp + c + 4);
            uint4 hq;
            hq.x = pack_h2(fmaxf(u0.x+v0.x+s0.x, 0.f), fmaxf(u0.y+v0.y+s0.y, 0.f));
            hq.y = pack_h2(fmaxf(u0.z+v0.z+s0.z, 0.f), fmaxf(u0.w+v0.w+s0.w, 0.f));
            hq.z = pack_h2(fmaxf(u1.x+v1.x+s1.x, 0.f), fmaxf(u1.y+v1.y+s1.y, 0.f));
            hq.w = pack_h2(fmaxf(u1.z+v1.z+s1.z, 0.f), fmaxf(u1.w+v1.w+s1.w, 0.f));
            *(uint4*)(hAh + row*SA + c) = hq;
        }
    }

    {
        const char* src = (const char*)wf;
        #pragma unroll
        for (int i = 0; i < 4; i++)
            cp16(wsm + (i*512 + tid)*16, src + (i*512 + tid)*16);
        CP_COMMIT();
    }

    float acc[2][8][4];

    #pragma unroll 1
    for (int sl = 0; sl < N_SLABS; sl++) {
        const int l   = sl >> 2;
        const int cur = sl & 1;
        __syncthreads();
        if (sl + 1 < N_SLABS) {
            const char* src = (const char*)wf + (size_t)(sl + 1) * WSLAB_B;
            uint32_t dst = wsm + (cur ^ 1) * WSLAB_B;
            #pragma unroll
            for (int i = 0; i < 4; i++)
                cp16(dst + (i*512 + tid)*16, src + (i*512 + tid)*16);
            CP_COMMIT();
            CP_WAIT1();
        } else {
            CP_WAIT0();
        }
        __syncthreads();

        if ((sl & 3) == 0) {
            #pragma unroll
            for (int mt = 0; mt < 2; mt++)
                #pragma unroll
                for (int j = 0; j < 8; j++)
                    #pragma unroll
                    for (int c = 0; c < 4; c++)
                        acc[mt][j][c] = 0.f;
        }

        const uint2* wslab = wbuf2 + cur * (WSLAB_B/8);
        const int kbase = (sl & 3) * 4;
        #pragma unroll
        for (int kk = 0; kk < 4; kk++) {
            const int kcol = (kbase + kk) * 16;
            uint32_t a[2][4];
            #pragma unroll
            for (int mt = 0; mt < 2; mt++) {
                int rA = mg*32 + mt*16 + (lane >> 2);
                const __half* base = hAh + rA*SA + kcol + 2*tig;
                a[mt][0] = *(const uint32_t*)(base);
                a[mt][1] = *(const uint32_t*)(base + 8*SA);
                a[mt][2] = *(const uint32_t*)(base + 8);
                a[mt][3] = *(const uint32_t*)(base + 8*SA + 8);
            }
            #pragma unroll
            for (int j = 0; j < 8; j++) {
                uint2 bb = wslab[(kk*32 + (ng*8 + j))*32 + lane];
                mma_f16(acc[0][j], a[0], bb.x, bb.y);
                mma_f16(acc[1][j], a[1], bb.x, bb.y);
            }
        }

        if ((sl & 3) == 3) {
            __syncthreads();
            if (l < 2) {
                const float* bl = biasS + l*HID;
                #pragma unroll
                for (int mt = 0; mt < 2; mt++) {
                    int rA = mg*32 + mt*16 + (lane >> 2);
                    #pragma unroll
                    for (int j = 0; j < 8; j++) {
                        int col = ng*64 + j*8 + 2*tig;
                        float b0 = bl[col], b1 = bl[col+1];
                        uint32_t lo = pack_h2(fmaxf(acc[mt][j][0] + b0, 0.f),
                                              fmaxf(acc[mt][j][1] + b1, 0.f));
                        uint32_t hi = pack_h2(fmaxf(acc[mt][j][2] + b0, 0.f),
                                              fmaxf(acc[mt][j][3] + b1, 0.f));
                        *(uint32_t*)(hAh + rA*SA + col)     = lo;
                        *(uint32_t*)(hAh + (rA+8)*SA + col) = hi;
                    }
                }
                __syncthreads();
            } else {
                const float* bl = biasS + 2*HID;
                #pragma unroll
                for (int j = 0; j < 8; j++) {
                    int col = ng*64 + j*8 + 2*tig;
                    float b0 = bl[col], b1 = bl[col+1];
                    float s0 = 0.f, s1 = 0.f;
                    #pragma unroll
                    for (int mt = 0; mt < 2; mt++) {
                        s0 += fmaxf(acc[mt][j][0] + b0, 0.f)
                            + fmaxf(acc[mt][j][2] + b0, 0.f);
                        s1 += fmaxf(acc[mt][j][1] + b1, 0.f)
                            + fmaxf(acc[mt][j][3] + b1, 0.f);
                    }
                    #pragma unroll
                    for (int off = 4; off < 32; off <<= 1) {
                        s0 += __shfl_xor_sync(0xFFFFFFFFu, s0, off);
                        s1 += __shfl_xor_sync(0xFFFFFFFFu, s1, off);
                    }
                    if (lane < 4) {
                        atomicAdd(&colsum[col],     s0);
                        atomicAdd(&colsum[col + 1], s1);
                    }
                }
            }
        }
    }

    __syncthreads();
    if (tid < HID) atomicAdd(&gsum[b*HID + tid], colsum[tid]);
}

// ---------------------------------------------------------------------------
// Launch #7: f_phi + restore accumulator invariant (zero gsum/bn arrays)
// ---------------------------------------------------------------------------
__global__ void fphi_kernel(float* __restrict__ gsum,
                            float* __restrict__ bnsum, float* __restrict__ bnsq,
                            const float* __restrict__ fw1, const float* __restrict__ fb1,
                            const float* __restrict__ fw2, const float* __restrict__ fb2,
                            const float* __restrict__ fw3, const float* __restrict__ fb3,
                            float* __restrict__ out) {
    __shared__ float ga[HID], gb[HID];
    int b = blockIdx.x, tid = threadIdx.x;
    ga[tid] = gsum[b*HID + tid] * (1.0f / (NN*NN));
    gsum[b*HID + tid] = 0.f;                 // restore invariant for next call
    if (b == 0 && tid < 4*CH) { bnsum[tid] = 0.f; bnsq[tid] = 0.f; }
    __syncthreads();
    float acc = fb1[tid];
    for (int f = 0; f < HID; f++) acc += ga[f] * fw1[f*HID + tid];
    gb[tid] = fmaxf(acc, 0.f);
    __syncthreads();
    acc = fb2[tid];
    for (int f = 0; f < HID; f++) acc += gb[f] * fw2[f*HID + tid];
    ga[tid] = fmaxf(acc, 0.f);
    __syncthreads();
    if (tid < AD) {
        float o = fb3[tid];
        for (int f = 0; f < HID; f++) o += ga[f] * fw3[f*AD + tid];
        out[b*AD + tid] = o;
    }
}

// ---------------------------------------------------------------------------
// Launch
// ---------------------------------------------------------------------------
extern "C" void kernel_launch(void* const* d_in, const int* in_sizes, int n_in,
                              void* d_out, int out_size) {
    (void)in_sizes; (void)n_in; (void)out_size;
    const float* img = (const float*)d_in[0];
    const float* q   = (const float*)d_in[1];
    const float* cw[4] = {(const float*)d_in[2],  (const float*)d_in[6],
                          (const float*)d_in[10], (const float*)d_in[14]};
    const float* cb[4] = {(const float*)d_in[3],  (const float*)d_in[7],
                          (const float*)d_in[11], (const float*)d_in[15]};
    const float* bg[4] = {(const float*)d_in[4],  (const float*)d_in[8],
                          (const float*)d_in[12], (const float*)d_in[16]};
    const float* bb[4] = {(const float*)d_in[5],  (const float*)d_in[9],
                          (const float*)d_in[13], (const float*)d_in[17]};
    const float* gw1 = (const float*)d_in[18]; const float* gb1 = (const float*)d_in[19];
    const float* gw2 = (const float*)d_in[20]; const float* gb2 = (const float*)d_in[21];
    const float* gw3 = (const float*)d_in[22]; const float* gb3 = (const float*)d_in[23];
    const float* gw4 = (const float*)d_in[24]; const float* gb4 = (const float*)d_in[25];
    const float* fw1 = (const float*)d_in[26]; const float* fb1 = (const float*)d_in[27];
    const float* fw2 = (const float*)d_in[28]; const float* fb2 = (const float*)d_in[29];
    const float* fw3 = (const float*)d_in[30]; const float* fb3 = (const float*)d_in[31];
    float* out = (float*)d_out;

    float *x1, *x2, *x3, *x4, *u, *v, *s, *gsum, *bnsum, *bnsq;
    uint2* wfp;
    cudaGetSymbolAddress((void**)&x1,    g_x1);
    cudaGetSymbolAddress((void**)&x2,    g_x2);
    cudaGetSymbolAddress((void**)&x3,    g_x3);
    cudaGetSymbolAddress((void**)&x4,    g_x4);
    cudaGetSymbolAddress((void**)&u,     g_u);
    cudaGetSymbolAddress((void**)&v,     g_v);
    cudaGetSymbolAddress((void**)&s,     g_s);
    cudaGetSymbolAddress((void**)&gsum,  g_gsum);
    cudaGetSymbolAddress((void**)&wfp,   g_wf);
    cudaGetSymbolAddress((void**)&bnsum, g_bnsum);
    cudaGetSymbolAddress((void**)&bnsq,  g_bnsq);

    cudaFuncSetAttribute(rn_mma_kernel,
                         cudaFuncAttributeMaxDynamicSharedMemorySize, DYN_RN);
    cudaFuncSetAttribute(conv_tile_kernel<24,24,64,32,8,6,64*64,true,false>,
                         cudaFuncAttributeMaxDynamicSharedMemorySize, CONVN_DYN);
    cudaFuncSetAttribute(conv_tile_kernel<24,24,32,16,8,6,32*32,true,false>,
                         cudaFuncAttributeMaxDynamicSharedMemorySize, CONVN_DYN);
    cudaFuncSetAttribute(conv_tile_kernel<24,24,16,8,8,6,16*16,true,false>,
                         cudaFuncAttributeMaxDynamicSharedMemorySize, CONVN_DYN);

    // #1: conv1 128->64 (16x16 tiles, 16/img) + wfrag tail; dyn 16528 (<48KB)
    conv_tile_kernel<3,24,128,64,16,24,0,false,true><<<BSZ*16, 256, CONV1_DYN>>>(
        img, cw[0], cb[0], nullptr, nullptr, nullptr, nullptr,
        x1, bnsum+0, bnsq+0, gw2, gw3, gw4, wfp);
    // #2: conv2 64->32 (8x8 tiles, 16/img, BN1 inline); dyn 55392 (opt-in)
    conv_tile_kernel<24,24,64,32,8,6,64*64,true,false><<<BSZ*16, 256, CONVN_DYN>>>(
        x1, cw[1], cb[1], bnsum+0, bnsq+0, bg[0], bb[0],
        x2, bnsum+CH, bnsq+CH, nullptr, nullptr, nullptr, nullptr);
    // #3: conv3 32->16 (8x8 tiles, 4/img); dyn 55392 (opt-in)
    conv_tile_kernel<24,24,32,16,8,6,32*32,true,false><<<BSZ*4, 256, CONVN_DYN>>>(
        x2, cw[2], cb[2], bnsum+CH, bnsq+CH, bg[1], bb[1],
        x3, bnsum+2*CH, bnsq+2*CH, nullptr, nullptr, nullptr, nullptr);
    // #4: conv4 16->8 (8x8 tile, 1/img); dyn 55392 (opt-in)
    conv_tile_kernel<24,24,16,8,8,6,16*16,true,false><<<BSZ, 256, CONVN_DYN>>>(
        x3, cw[3], cb[3], bnsum+2*CH, bnsq+2*CH, bg[2], bb[2],
        x4, bnsum+3*CH, bnsq+3*CH, nullptr, nullptr, nullptr, nullptr);
    // #5: u/v (+s), BN4 finalize inline
    uv_kernel<<<BSZ*NN, 256>>>(x4, bnsum+3*CH, bnsq+3*CH, bg[3], bb[3],
                               q, gw1, gb1, u, v, s);
    // #6: the core
    rn_mma_kernel<<<BSZ*NN/2, 512, DYN_RN>>>(u, v, s, gsum, wfp, gb2, gb3, gb4);
    // #7: f_phi + re-zero accumulators
    fphi_kernel<<<BSZ, 256>>>(gsum, bnsum, bnsq,
                              fw1, fb1, fw2, fb2, fw3, fb3, out);
}